// round 14
// baseline (speedup 1.0000x reference)
#include <cuda_runtime.h>
#include <math.h>

#define BB 4
#define EE 100000
#define TT 100000
#define DD 64
#define EPSV 1e-6f
#define FCAP 4096
#define LCAP 1024
#define KMAX 7

// Scratch — zero at module load; every executed launch restores the zeros it dirties.
__device__ __align__(16) float g_ep0[BB * EE];
__device__ __align__(16) float g_hist[(size_t)BB * EE * DD];   // sparse-touched
__device__ int g_cf1, g_cf2;                 // frontier (distinct (b,ent)) counts
__device__ int g_front1[FCAP], g_front2[FCAP];
__device__ int g_count;                      // barrier counter (self-resetting)

__device__ __forceinline__ float sigmoidf_(float x) { return 1.f / (1.f + expf(-x)); }

// monotonic-counter grid barrier: wait until g_count reaches `target` (bare spin)
__device__ __forceinline__ void gbar(int target) {
    __syncthreads();
    if (threadIdx.x == 0) {
        __threadfence();
        atomicAdd(&g_count, 1);
        while (*(volatile int*)&g_count < target) {}
        __threadfence();
    }
    __syncthreads();
}

// lean block-parallel GRU for one active (b, edge). Caller syncs between edges.
// STEP==1 accumulates objp directly into out[] (zeroed in Phase A).
template <int STEP>
__device__ __forceinline__ void block_gru(
    int code, const int* __restrict__ kb, const float* __restrict__ rel_emb,
    const float* __restrict__ w_ih, const float* __restrict__ b_ih,
    const float* __restrict__ w_hh, const float* __restrict__ b_hh,
    const float* __restrict__ w_cls, const float* __restrict__ b_cls,
    const float* __restrict__ W_step, const float* __restrict__ b_step,
    const int* __restrict__ query, float* __restrict__ out,
    float* s_x, float* s_hp, float4* s_rel4, float4* s_h4, float* s_cq,
    int tid) {
    int b = code >> 20, t = code & 0xFFFFF;
    int s = __ldg(&kb[3 * t]);
    int o = __ldg(&kb[3 * t + 1]);
    int r = __ldg(&kb[3 * t + 2]);
    float ep = 0.f;
    if (STEP == 1) ep = g_ep0[b * EE + s];
    if (tid < DD / 4) s_rel4[tid] = __ldg((const float4*)(rel_emb + r * DD) + tid);
    if (STEP == 1 && tid >= 32 && tid < 32 + DD / 4) {
        float inv = 1.f / (ep + EPSV);
        float4 h4 = *((const float4*)(g_hist + (size_t)(b * EE + s) * DD) + (tid - 32));
        h4.x *= inv; h4.y *= inv; h4.z *= inv; h4.w *= inv;
        s_h4[tid - 32] = h4;
    }
    __syncthreads();
    if (tid < 3 * DD) {                       // 192 row-threads: x_proj + h_proj
        const float4* w = (const float4*)(w_ih + tid * DD);
        float a0 = __ldg(&b_ih[tid]), a1 = 0.f;
        #pragma unroll
        for (int k = 0; k < DD / 4; k += 2) {
            float4 wv = __ldg(w + k);     float4 rv = s_rel4[k];
            a0 = fmaf(wv.x, rv.x, a0); a0 = fmaf(wv.y, rv.y, a0);
            a0 = fmaf(wv.z, rv.z, a0); a0 = fmaf(wv.w, rv.w, a0);
            float4 wu = __ldg(w + k + 1); float4 ru = s_rel4[k + 1];
            a1 = fmaf(wu.x, ru.x, a1); a1 = fmaf(wu.y, ru.y, a1);
            a1 = fmaf(wu.z, ru.z, a1); a1 = fmaf(wu.w, ru.w, a1);
        }
        s_x[tid] = a0 + a1;
        float h0 = __ldg(&b_hh[tid]), h1 = 0.f;
        if (STEP == 1) {
            const float4* wh = (const float4*)(w_hh + tid * DD);
            #pragma unroll
            for (int k = 0; k < DD / 4; k += 2) {
                float4 wv = __ldg(wh + k);     float4 hv = s_h4[k];
                h0 = fmaf(wv.x, hv.x, h0); h0 = fmaf(wv.y, hv.y, h0);
                h0 = fmaf(wv.z, hv.z, h0); h0 = fmaf(wv.w, hv.w, h0);
                float4 wu = __ldg(wh + k + 1); float4 hu = s_h4[k + 1];
                h1 = fmaf(wu.x, hu.x, h1); h1 = fmaf(wu.y, hu.y, h1);
                h1 = fmaf(wu.z, hu.z, h1); h1 = fmaf(wu.w, hu.w, h1);
            }
        }
        s_hp[tid] = h0 + h1;
    } else {                                  // 64 cq-threads: tanh(q@W_s+b_s)*w_cls
        int d = tid - 3 * DD;
        int qb = __ldg(&query[b]);
        const float* qe = rel_emb + qb * DD;
        float c0 = __ldg(&b_step[STEP * DD + d]), c1 = 0.f;
        const float* W = W_step + STEP * DD * DD + d;
        #pragma unroll
        for (int k = 0; k < DD; k += 2) {
            c0 = fmaf(__ldg(&qe[k]), __ldg(&W[k * DD]), c0);
            c1 = fmaf(__ldg(&qe[k + 1]), __ldg(&W[(k + 1) * DD]), c1);
        }
        s_cq[d] = tanhf(c0 + c1) * __ldg(&w_cls[d]);
    }
    __syncthreads();
    if (tid < 32) {                           // warp-0 epilogue: 2 dims per lane
        int d0 = tid, d1 = tid + 32;
        float hd0 = 0.f, hd1 = 0.f;
        if (STEP == 1) { hd0 = ((const float*)s_h4)[d0]; hd1 = ((const float*)s_h4)[d1]; }
        float rg0 = sigmoidf_(s_x[d0] + s_hp[d0]);
        float zg0 = sigmoidf_(s_x[DD + d0] + s_hp[DD + d0]);
        float ng0 = tanhf(s_x[2 * DD + d0] + rg0 * s_hp[2 * DD + d0]);
        float tr0 = (1.f - zg0) * ng0 + zg0 * hd0;
        float rg1 = sigmoidf_(s_x[d1] + s_hp[d1]);
        float zg1 = sigmoidf_(s_x[DD + d1] + s_hp[DD + d1]);
        float ng1 = tanhf(s_x[2 * DD + d1] + rg1 * s_hp[2 * DD + d1]);
        float tr1 = (1.f - zg1) * ng1 + zg1 * hd1;
        float v = tr0 * s_cq[d0] + tr1 * s_cq[d1];
        #pragma unroll
        for (int off = 16; off; off >>= 1) v += __shfl_xor_sync(0xFFFFFFFFu, v, off);
        float objp = 0.f;
        if (tid == 0) {
            float le = STEP ? (ep > 1.f ? 1.f : ep) : 1.f;   // step0: start one-hot
            float p = sigmoidf_(v + __ldg(b_cls));
            objp = le * p;
            if (STEP == 0) {
                float old = atomicAdd(&g_ep0[b * EE + o], objp);
                if (old == 0.f) { int j = atomicAdd(&g_cf1, 1); if (j < FCAP) g_front1[j] = (b << 20) | o; }
            } else {
                float old = atomicAdd(&out[b * EE + o], objp);   // objp > 0 always
                if (old == 0.f) { int j = atomicAdd(&g_cf2, 1); if (j < FCAP) g_front2[j] = (b << 20) | o; }
            }
        }
        objp = __shfl_sync(0xFFFFFFFFu, objp, 0);
        if (STEP == 0) {
            float* hrow = g_hist + (size_t)(b * EE + o) * DD;
            atomicAdd(&hrow[d0], tr0 * objp);
            atomicAdd(&hrow[d1], tr1 * objp);
        }
    }
}

__global__ void __launch_bounds__(256, 1) k_all(
    int nb,
    const float* __restrict__ start, const float* __restrict__ rel_emb,
    const float* __restrict__ W_step, const float* __restrict__ b_step,
    const float* __restrict__ w_ih, const float* __restrict__ w_hh,
    const float* __restrict__ b_ih, const float* __restrict__ b_hh,
    const float* __restrict__ w_cls, const float* __restrict__ b_cls,
    const int* __restrict__ query, const int* __restrict__ kb,
    float* __restrict__ out) {
    __shared__ float s_x[3 * DD], s_hp[3 * DD];
    __shared__ float4 s_rel4[DD / 4], s_h4[DD / 4];
    __shared__ float s_cq[DD];
    __shared__ int s_list[LCAP];
    __shared__ int s_n, s_last;
    int tid = threadIdx.x;
    int gtid = blockIdx.x * 256 + tid;
    int gsz = nb * 256;
    int kcnt = (TT + gsz - 1) / gsz;          // edge slots per thread (covers ALL of TT)

    // ==== Phase A (barrier-free): cache sub; batch-issue start probes;
    //      dense out zero; block-local step-0 GRU ============================
    if (tid == 0) s_n = 0;
    int sub[KMAX];
    #pragma unroll
    for (int k = 0; k < KMAX; k++) {
        int t = gtid + k * gsz;
        sub[k] = (k < kcnt && t < TT) ? __ldg(&kb[3 * t]) : -1;
    }
    float prob[KMAX][BB];                     // all scattered probes in flight at once
    #pragma unroll
    for (int k = 0; k < KMAX; k++) {
        #pragma unroll
        for (int b = 0; b < BB; b++)
            prob[k][b] = (k < kcnt && sub[k] >= 0) ? __ldg(&start[b * EE + sub[k]]) : 0.f;
    }
    {   // dense zero of out (overlaps probe latency)
        const float4 z4 = make_float4(0.f, 0.f, 0.f, 0.f);
        for (int i = gtid; i < BB * EE / 4; i += gsz)
            ((float4*)out)[i] = z4;                      // step-1 GRUs atomicAdd into it
    }
    __syncthreads();                                      // s_n init visible
    for (int k = 0; k < kcnt; k++) {
        #pragma unroll
        for (int b = 0; b < BB; b++) {
            if (prob[k][b] != 0.f) {                      // start is one-hot per batch
                int j = atomicAdd(&s_n, 1);
                if (j < LCAP) s_list[j] = (b << 20) | (gtid + k * gsz);
            }
        }
    }
    __syncthreads();
    {
        int n = min(s_n, LCAP);
        for (int e = 0; e < n; e++) {
            if (e) __syncthreads();
            block_gru<0>(s_list[e], kb, rel_emb, w_ih, b_ih, w_hh, b_hh,
                         w_cls, b_cls, W_step, b_step, query, out,
                         s_x, s_hp, s_rel4, s_h4, s_cq, tid);
        }
    }
    gbar(nb);   // the ONE irreducible step-0 -> step-1 barrier

    // ==== Phase B: step 1 — direct frontier reads (one cache line), register
    //      compare, block-local GRU, objp accumulated straight into out ======
    if (tid == 0) s_n = 0;
    __syncthreads();
    {
        int F1 = min(g_cf1, FCAP);
        for (int f = 0; f < F1; f++) {
            int code = __ldg(&g_front1[f]);               // L1-hit after first touch
            int ent = code & 0xFFFFF;
            int bhi = code & 0xFFF00000;
            for (int k = 0; k < kcnt; k++) {
                if (sub[k] == ent) {
                    int j = atomicAdd(&s_n, 1);
                    if (j < LCAP) s_list[j] = bhi | (gtid + k * gsz);
                }
            }
        }
    }
    __syncthreads();
    {
        int n = min(s_n, LCAP);
        for (int e = 0; e < n; e++) {
            if (e) __syncthreads();
            block_gru<1>(s_list[e], kb, rel_emb, w_ih, b_ih, w_hh, b_hh,
                         w_cls, b_cls, W_step, b_step, query, out,
                         s_x, s_hp, s_rel4, s_h4, s_cq, tid);
        }
    }

    // ==== Terminal: last-arriving block clamps out + cleans up + resets ======
    __syncthreads();
    if (tid == 0) {
        __threadfence();
        int old = atomicAdd(&g_count, 1);
        s_last = (old == 2 * nb - 1);
    }
    __syncthreads();
    if (s_last) {
        __threadfence();                       // acquire: see all blocks' writes
        int F2 = min(g_cf2, FCAP);
        for (int j = tid; j < F2; j += 256) {  // clamp touched out entries
            int code = g_front2[j];
            int idx = (code >> 20) * EE + (code & 0xFFFFF);
            float x = out[idx];
            if (x > 1.f) out[idx] = 1.f;
        }
        int F1 = min(g_cf1, FCAP);
        int wid = tid >> 5, lane = tid & 31;
        for (int j = wid; j < F1; j += 8) {    // zero ep0 + hist rows
            int code = g_front1[j];
            size_t idx = (size_t)((code >> 20) * EE + (code & 0xFFFFF));
            if (lane == 0) g_ep0[idx] = 0.f;
            ((float2*)(g_hist + idx * DD))[lane] = make_float2(0.f, 0.f);
        }
        __syncthreads();
        if (tid == 0) {
            g_cf1 = 0; g_cf2 = 0;
            __threadfence();
            g_count = 0;                       // reset for next replay
        }
    }
}

extern "C" void kernel_launch(void* const* d_in, const int* in_sizes, int n_in,
                              void* d_out, int out_size) {
    (void)in_sizes; (void)n_in; (void)out_size;
    const float* start   = (const float*)d_in[0];
    const float* rel_emb = (const float*)d_in[1];
    const float* W_step  = (const float*)d_in[2];
    const float* b_step  = (const float*)d_in[3];
    const float* w_ih    = (const float*)d_in[4];
    const float* w_hh    = (const float*)d_in[5];
    const float* b_ih    = (const float*)d_in[6];
    const float* b_hh    = (const float*)d_in[7];
    const float* w_cls   = (const float*)d_in[8];
    const float* b_cls   = (const float*)d_in[9];
    const int*   query   = (const int*)d_in[10];
    const int*   kb      = (const int*)d_in[11];
    float* out = (float*)d_out;

    int dev = 0;
    cudaGetDevice(&dev);
    int sms = 0;
    if (cudaDeviceGetAttribute(&sms, cudaDevAttrMultiProcessorCount, dev) != cudaSuccess || sms <= 0)
        sms = 64;
    int nb = sms;   // one block per SM; KMAX=7 covers TT down to nb=56

    k_all<<<nb, 256>>>(nb, start, rel_emb, W_step, b_step, w_ih, w_hh,
                       b_ih, b_hh, w_cls, b_cls, query, kb, out);
}

// round 15
// speedup vs baseline: 1.0611x; 1.0611x over previous
#include <cuda_runtime.h>
#include <math.h>

#define BB 4
#define EE 100000
#define TT 100000
#define DD 64
#define EPSV 1e-6f
#define FCAP 4096
#define LCAP 1024
#define SFC 512
#define KMAX 7

// Scratch — zero at module load; every executed launch restores the zeros it dirties.
__device__ __align__(16) float g_ep0[BB * EE];
__device__ __align__(16) float g_hist[(size_t)BB * EE * DD];   // sparse-touched
__device__ int g_cf1, g_cf2;                 // frontier (distinct (b,ent)) counts
__device__ int g_front1[FCAP], g_front2[FCAP];
__device__ int g_count;                      // barrier counter (self-resetting)

__device__ __forceinline__ float sigmoidf_(float x) { return 1.f / (1.f + expf(-x)); }

// monotonic-counter grid barrier: wait until g_count reaches `target` (bare spin)
__device__ __forceinline__ void gbar(int target) {
    __syncthreads();
    if (threadIdx.x == 0) {
        __threadfence();
        atomicAdd(&g_count, 1);
        while (*(volatile int*)&g_count < target) {}
        __threadfence();
    }
    __syncthreads();
}

// lean block-parallel GRU for one active (b, edge).
// STEP==1 accumulates objp directly into out[] (zeroed in Phase A).
template <int STEP>
__device__ __forceinline__ void block_gru(
    int code, const int* __restrict__ kb, const float* __restrict__ rel_emb,
    const float* __restrict__ w_ih, const float* __restrict__ b_ih,
    const float* __restrict__ w_hh, const float* __restrict__ b_hh,
    const float* __restrict__ w_cls, const float* __restrict__ b_cls,
    const float* __restrict__ W_step, const float* __restrict__ b_step,
    const int* __restrict__ query, float* __restrict__ out,
    float* s_x, float* s_hp, float4* s_rel4, float4* s_h4, float* s_cq,
    int tid) {
    int b = code >> 20, t = code & 0xFFFFF;
    int s = __ldg(&kb[3 * t]);
    int o = __ldg(&kb[3 * t + 1]);
    int r = __ldg(&kb[3 * t + 2]);
    float ep = 0.f;
    if (STEP == 1) ep = g_ep0[b * EE + s];
    __syncthreads();                          // guard smem reuse across edges
    if (tid < DD / 4) s_rel4[tid] = __ldg((const float4*)(rel_emb + r * DD) + tid);
    if (STEP == 1 && tid >= 32 && tid < 32 + DD / 4) {
        float inv = 1.f / (ep + EPSV);
        float4 h4 = *((const float4*)(g_hist + (size_t)(b * EE + s) * DD) + (tid - 32));
        h4.x *= inv; h4.y *= inv; h4.z *= inv; h4.w *= inv;
        s_h4[tid - 32] = h4;
    }
    __syncthreads();
    if (tid < 3 * DD) {                       // 192 row-threads: x_proj + h_proj
        const float4* w = (const float4*)(w_ih + tid * DD);
        float a0 = __ldg(&b_ih[tid]), a1 = 0.f;
        #pragma unroll
        for (int k = 0; k < DD / 4; k += 2) {
            float4 wv = __ldg(w + k);     float4 rv = s_rel4[k];
            a0 = fmaf(wv.x, rv.x, a0); a0 = fmaf(wv.y, rv.y, a0);
            a0 = fmaf(wv.z, rv.z, a0); a0 = fmaf(wv.w, rv.w, a0);
            float4 wu = __ldg(w + k + 1); float4 ru = s_rel4[k + 1];
            a1 = fmaf(wu.x, ru.x, a1); a1 = fmaf(wu.y, ru.y, a1);
            a1 = fmaf(wu.z, ru.z, a1); a1 = fmaf(wu.w, ru.w, a1);
        }
        s_x[tid] = a0 + a1;
        float h0 = __ldg(&b_hh[tid]), h1 = 0.f;
        if (STEP == 1) {
            const float4* wh = (const float4*)(w_hh + tid * DD);
            #pragma unroll
            for (int k = 0; k < DD / 4; k += 2) {
                float4 wv = __ldg(wh + k);     float4 hv = s_h4[k];
                h0 = fmaf(wv.x, hv.x, h0); h0 = fmaf(wv.y, hv.y, h0);
                h0 = fmaf(wv.z, hv.z, h0); h0 = fmaf(wv.w, hv.w, h0);
                float4 wu = __ldg(wh + k + 1); float4 hu = s_h4[k + 1];
                h1 = fmaf(wu.x, hu.x, h1); h1 = fmaf(wu.y, hu.y, h1);
                h1 = fmaf(wu.z, hu.z, h1); h1 = fmaf(wu.w, hu.w, h1);
            }
        }
        s_hp[tid] = h0 + h1;
    } else {                                  // 64 cq-threads: tanh(q@W_s+b_s)*w_cls
        int d = tid - 3 * DD;
        int qb = __ldg(&query[b]);
        const float* qe = rel_emb + qb * DD;
        float c0 = __ldg(&b_step[STEP * DD + d]), c1 = 0.f;
        const float* W = W_step + STEP * DD * DD + d;
        #pragma unroll
        for (int k = 0; k < DD; k += 2) {
            c0 = fmaf(__ldg(&qe[k]), __ldg(&W[k * DD]), c0);
            c1 = fmaf(__ldg(&qe[k + 1]), __ldg(&W[(k + 1) * DD]), c1);
        }
        s_cq[d] = tanhf(c0 + c1) * __ldg(&w_cls[d]);
    }
    __syncthreads();
    if (tid < 32) {                           // warp-0 epilogue: 2 dims per lane
        int d0 = tid, d1 = tid + 32;
        float hd0 = 0.f, hd1 = 0.f;
        if (STEP == 1) { hd0 = ((const float*)s_h4)[d0]; hd1 = ((const float*)s_h4)[d1]; }
        float rg0 = sigmoidf_(s_x[d0] + s_hp[d0]);
        float zg0 = sigmoidf_(s_x[DD + d0] + s_hp[DD + d0]);
        float ng0 = tanhf(s_x[2 * DD + d0] + rg0 * s_hp[2 * DD + d0]);
        float tr0 = (1.f - zg0) * ng0 + zg0 * hd0;
        float rg1 = sigmoidf_(s_x[d1] + s_hp[d1]);
        float zg1 = sigmoidf_(s_x[DD + d1] + s_hp[DD + d1]);
        float ng1 = tanhf(s_x[2 * DD + d1] + rg1 * s_hp[2 * DD + d1]);
        float tr1 = (1.f - zg1) * ng1 + zg1 * hd1;
        float v = tr0 * s_cq[d0] + tr1 * s_cq[d1];
        #pragma unroll
        for (int off = 16; off; off >>= 1) v += __shfl_xor_sync(0xFFFFFFFFu, v, off);
        float objp = 0.f;
        if (tid == 0) {
            float le = STEP ? (ep > 1.f ? 1.f : ep) : 1.f;   // step0: start one-hot
            float p = sigmoidf_(v + __ldg(b_cls));
            objp = le * p;
            if (STEP == 0) {
                float old = atomicAdd(&g_ep0[b * EE + o], objp);
                if (old == 0.f) { int j = atomicAdd(&g_cf1, 1); if (j < FCAP) g_front1[j] = (b << 20) | o; }
            } else {
                float old = atomicAdd(&out[b * EE + o], objp);   // objp > 0 always
                if (old == 0.f) { int j = atomicAdd(&g_cf2, 1); if (j < FCAP) g_front2[j] = (b << 20) | o; }
            }
        }
        objp = __shfl_sync(0xFFFFFFFFu, objp, 0);
        if (STEP == 0) {
            float* hrow = g_hist + (size_t)(b * EE + o) * DD;
            atomicAdd(&hrow[d0], tr0 * objp);
            atomicAdd(&hrow[d1], tr1 * objp);
        }
    }
}

__global__ void __launch_bounds__(256, 1) k_all(
    int nb,
    const float* __restrict__ start, const float* __restrict__ rel_emb,
    const float* __restrict__ W_step, const float* __restrict__ b_step,
    const float* __restrict__ w_ih, const float* __restrict__ w_hh,
    const float* __restrict__ b_ih, const float* __restrict__ b_hh,
    const float* __restrict__ w_cls, const float* __restrict__ b_cls,
    const int* __restrict__ query, const int* __restrict__ kb,
    float* __restrict__ out) {
    __shared__ float s_x[3 * DD], s_hp[3 * DD];
    __shared__ float4 s_rel4[DD / 4], s_h4[DD / 4];
    __shared__ float s_cq[DD];
    __shared__ int s_list[LCAP];
    __shared__ int s_front[SFC];
    __shared__ int s_n, s_last;
    int tid = threadIdx.x;
    int gtid = blockIdx.x * 256 + tid;
    int gsz = nb * 256;
    int kcnt = (TT + gsz - 1) / gsz;          // edge slots per thread (covers ALL of TT)

    // ==== Phase A (barrier-free): cache sub; dense out zero; probe start;
    //      block-local step-0 GRU =============================================
    if (tid == 0) s_n = 0;
    int sub[KMAX];
    #pragma unroll
    for (int k = 0; k < KMAX; k++) {
        int t = gtid + k * gsz;
        sub[k] = (k < kcnt && t < TT) ? __ldg(&kb[3 * t]) : -1;
    }
    {   // dense zero of out (overlaps sub/probe load latency)
        const float4 z4 = make_float4(0.f, 0.f, 0.f, 0.f);
        for (int i = gtid; i < BB * EE / 4; i += gsz)
            ((float4*)out)[i] = z4;                      // step-1 GRUs atomicAdd into it
    }
    __syncthreads();                                      // s_n init visible
    for (int k = 0; k < kcnt; k++) {
        int t = gtid + k * gsz;
        int s = sub[k];
        if (s >= 0) {
            #pragma unroll
            for (int b = 0; b < BB; b++) {
                if (__ldg(&start[b * EE + s]) != 0.f) {   // start is one-hot per batch
                    int j = atomicAdd(&s_n, 1);
                    if (j < LCAP) s_list[j] = (b << 20) | t;
                }
            }
        }
    }
    __syncthreads();
    {
        int n = min(s_n, LCAP);
        for (int e = 0; e < n; e++)
            block_gru<0>(s_list[e], kb, rel_emb, w_ih, b_ih, w_hh, b_hh,
                         w_cls, b_cls, W_step, b_step, query, out,
                         s_x, s_hp, s_rel4, s_h4, s_cq, tid);
    }
    gbar(nb);   // the ONE irreducible step-0 -> step-1 barrier

    // ==== Phase B: step 1 — register compare vs frontier-1, block-local GRU,
    //      objp accumulated straight into out =================================
    if (tid == 0) s_n = 0;
    __syncthreads();
    {
        int F1 = min(g_cf1, FCAP);
        for (int j = tid; j < F1 && j < SFC; j += 256) s_front[j] = g_front1[j];
        __syncthreads();
        for (int f = 0; f < F1; f++) {
            int code = (f < SFC) ? s_front[f] : g_front1[f];
            int ent = code & 0xFFFFF;
            int bhi = code & 0xFFF00000;
            for (int k = 0; k < kcnt; k++) {
                if (sub[k] == ent) {
                    int j = atomicAdd(&s_n, 1);
                    if (j < LCAP) s_list[j] = bhi | (gtid + k * gsz);
                }
            }
        }
    }
    __syncthreads();
    {
        int n = min(s_n, LCAP);
        for (int e = 0; e < n; e++)
            block_gru<1>(s_list[e], kb, rel_emb, w_ih, b_ih, w_hh, b_hh,
                         w_cls, b_cls, W_step, b_step, query, out,
                         s_x, s_hp, s_rel4, s_h4, s_cq, tid);
    }

    // ==== Terminal: last-arriving block clamps out + cleans up + resets ======
    __syncthreads();
    if (tid == 0) {
        __threadfence();
        int old = atomicAdd(&g_count, 1);
        s_last = (old == 2 * nb - 1);
    }
    __syncthreads();
    if (s_last) {
        __threadfence();                       // acquire: see all blocks' writes
        int F2 = min(g_cf2, FCAP);
        for (int j = tid; j < F2; j += 256) {  // clamp touched out entries
            int code = g_front2[j];
            int idx = (code >> 20) * EE + (code & 0xFFFFF);
            float x = out[idx];
            if (x > 1.f) out[idx] = 1.f;
        }
        int F1 = min(g_cf1, FCAP);
        int wid = tid >> 5, lane = tid & 31;
        for (int j = wid; j < F1; j += 8) {    // zero ep0 + hist rows
            int code = g_front1[j];
            size_t idx = (size_t)((code >> 20) * EE + (code & 0xFFFFF));
            if (lane == 0) g_ep0[idx] = 0.f;
            ((float2*)(g_hist + idx * DD))[lane] = make_float2(0.f, 0.f);
        }
        __syncthreads();
        if (tid == 0) {
            g_cf1 = 0; g_cf2 = 0;
            __threadfence();
            g_count = 0;                       // reset for next replay
        }
    }
}

extern "C" void kernel_launch(void* const* d_in, const int* in_sizes, int n_in,
                              void* d_out, int out_size) {
    (void)in_sizes; (void)n_in; (void)out_size;
    const float* start   = (const float*)d_in[0];
    const float* rel_emb = (const float*)d_in[1];
    const float* W_step  = (const float*)d_in[2];
    const float* b_step  = (const float*)d_in[3];
    const float* w_ih    = (const float*)d_in[4];
    const float* w_hh    = (const float*)d_in[5];
    const float* b_ih    = (const float*)d_in[6];
    const float* b_hh    = (const float*)d_in[7];
    const float* w_cls   = (const float*)d_in[8];
    const float* b_cls   = (const float*)d_in[9];
    const int*   query   = (const int*)d_in[10];
    const int*   kb      = (const int*)d_in[11];
    float* out = (float*)d_out;

    int dev = 0;
    cudaGetDevice(&dev);
    int sms = 0;
    if (cudaDeviceGetAttribute(&sms, cudaDevAttrMultiProcessorCount, dev) != cudaSuccess || sms <= 0)
        sms = 64;
    int nb = sms;   // one block per SM; KMAX=7 covers TT down to nb=56

    k_all<<<nb, 256>>>(nb, start, rel_emb, W_step, b_step, w_ih, w_hh,
                       b_ih, b_hh, w_cls, b_cls, query, kb, out);
}